// round 9
// baseline (speedup 1.0000x reference)
#include <cuda_runtime.h>
#include <math.h>

#define NBLK 128
#define NTHR 1024
#define MAXN 4096
#define MAXS 27
#define NGRID 10
#define NCELL (NGRID * NGRID * NGRID)
#define MAXPA 192
#define MAXM 7424   // capacity of shared image table (expected M ~6500)

__device__ int g_cnt[MAXN];
__device__ unsigned g_barcnt, g_bargen;

#define MUL(a, b) __fmul_rn((a), (b))
#define ADD(a, b) __fadd_rn((a), (b))
#define SUB(a, b) __fsub_rn((a), (b))
#define DIV(a, b) __fdiv_rn((a), (b))

__device__ __forceinline__ unsigned fkey(float f) {
    unsigned u = __float_as_uint(f);
    return (u & 0x80000000u) ? ~u : (u | 0x80000000u);
}
__device__ __forceinline__ float fdec(unsigned k) {
    unsigned u = (k & 0x80000000u) ? (k & 0x7fffffffu) : ~k;
    return __uint_as_float(u);
}

// grid barrier: all NBLK blocks co-resident (128 blocks, 1/SM)
__device__ __forceinline__ void gbar(unsigned target) {
    __syncthreads();
    if (threadIdx.x == 0) {
        __threadfence();
        unsigned a = atomicAdd(&g_barcnt, 1u);
        if (a == NBLK - 1u) {
            g_barcnt = 0u;
            __threadfence();
            atomicExch(&g_bargen, target);
        } else {
            while ((int)(*(volatile unsigned*)&g_bargen - target) < 0) { }
            __threadfence();
        }
    }
    __syncthreads();
}

// exclusive scan over 1024 threads; 3 syncthreads (leading sync included)
__device__ __forceinline__ int scanExcl1024(int v, int* stmp, int lane, int wid) {
    __syncthreads();
    int x = v;
#pragma unroll
    for (int o = 1; o < 32; o <<= 1) {
        int y = __shfl_up_sync(0xffffffffu, x, o);
        if (lane >= o) x += y;
    }
    if (lane == 31) stmp[wid] = x;
    __syncthreads();
    if (wid == 0) {
        int s = stmp[lane];
#pragma unroll
        for (int o = 1; o < 32; o <<= 1) {
            int y = __shfl_up_sync(0xffffffffu, s, o);
            if (lane >= o) s += y;
        }
        stmp[lane] = s;
    }
    __syncthreads();
    int base = wid ? stmp[wid - 1] : 0;
    return base + x - v;
}

extern __shared__ char dynsmem[];

__global__ __launch_bounds__(NTHR, 1)
void k_all(const float* __restrict__ cell, const int* __restrict__ period,
           const float* __restrict__ coords, const float* __restrict__ mass,
           int N, int P, float* __restrict__ out) {
    __shared__ float sinv[9], sfrac0[3], sshifts[MAXS * 3];
    __shared__ float scom[3], sminc[3], smaxc[3];
    __shared__ int   sS;
    __shared__ int   stmp[33];
    __shared__ unsigned skey6[32][6];
    __shared__ int   sWoff[32];

    // dynamic shared carve-up
    float4* s_img4 = (float4*)dynsmem;                     // MAXM*16 = 118784B (bucketed images)
    double* sd     = (double*)dynsmem;                     // alias: COM tree (dead before images)
    float*  s_wx   = (float*)(dynsmem + MAXM * 16);
    float*  s_wy   = s_wx + N;
    float*  s_wz   = s_wy + N;
    char*   sjbase = dynsmem + MAXM * 16 + 3 * 4 * N;      // 24576B region
    int*    sj     = (int*)sjbase;                         // per-warp hit lists (search/write)
    int*    s_hist = (int*)sjbase;                         // alias: cell histogram (dead before search)
    int*    s_fill = (int*)(sjbase + 8192);                // alias: scatter cursors (dead before search)
    int*    scoff  = (int*)(sjbase + 24576);               // (NCELL+8)*4 — live through search

    const int t = threadIdx.x, b = blockIdx.x;
    const int lane = t & 31, wid = t >> 5;
    unsigned gen = *(volatile unsigned*)&g_bargen;

    // ================= PHASE A (block-local, bit-identical to R8) =================
    if (t == 0) {
        float m00 = cell[0], m01 = cell[1], m02 = cell[2];
        float m10 = cell[3], m11 = cell[4], m12 = cell[5];
        float m20 = cell[6], m21 = cell[7], m22 = cell[8];
        float c00 = SUB(MUL(m11, m22), MUL(m12, m21));
        float c10 = SUB(MUL(m12, m20), MUL(m10, m22));
        float c20 = SUB(MUL(m10, m21), MUL(m11, m20));
        float det = ADD(ADD(MUL(m00, c00), MUL(m01, c10)), MUL(m02, c20));
        sinv[0] = DIV(c00, det);
        sinv[1] = DIV(SUB(MUL(m02, m21), MUL(m01, m22)), det);
        sinv[2] = DIV(SUB(MUL(m01, m12), MUL(m02, m11)), det);
        sinv[3] = DIV(c10, det);
        sinv[4] = DIV(SUB(MUL(m00, m22), MUL(m02, m20)), det);
        sinv[5] = DIV(SUB(MUL(m02, m10), MUL(m00, m12)), det);
        sinv[6] = DIV(c20, det);
        sinv[7] = DIV(SUB(MUL(m01, m20), MUL(m00, m21)), det);
        sinv[8] = DIV(SUB(MUL(m00, m11), MUL(m01, m10)), det);
        float x0 = coords[0], y0 = coords[1], z0 = coords[2];
        for (int d = 0; d < 3; d++)
            sfrac0[d] = ADD(ADD(MUL(x0, sinv[0 + d]), MUL(y0, sinv[3 + d])), MUL(z0, sinv[6 + d]));
        int nrep[3];
        for (int i = 0; i < 3; i++) {
            float r = DIV(5.0f, fabsf(cell[0 + i]));
            float r1 = DIV(5.0f, fabsf(cell[3 + i]));
            float r2 = DIV(5.0f, fabsf(cell[6 + i]));
            if (r1 < r) r = r1;
            if (r2 < r) r = r2;
            nrep[i] = (int)ceilf(r) * period[i];
        }
        int idx = 0;
        for (int a = -nrep[0]; a <= nrep[0]; a++)
            for (int bb = -nrep[1]; bb <= nrep[1]; bb++)
                for (int c = -nrep[2]; c <= nrep[2]; c++) {
                    if (idx < MAXS) {
                        float fa = (float)a, fb = (float)bb, fc = (float)c;
                        for (int d = 0; d < 3; d++)
                            sshifts[idx * 3 + d] =
                                ADD(ADD(MUL(fa, cell[0 + d]), MUL(fb, cell[3 + d])), MUL(fc, cell[6 + d]));
                    }
                    idx++;
                }
        sS = (idx > MAXS) ? MAXS : idx;
    }
    __syncthreads();

    // wrap ALL atoms into shared (redundant per block; bit-identical everywhere)
    for (int i = t; i < N; i += NTHR) {
        float x = coords[i * 3 + 0], y = coords[i * 3 + 1], z = coords[i * 3 + 2];
        float f[3];
        for (int d = 0; d < 3; d++)
            f[d] = ADD(ADD(MUL(x, sinv[0 + d]), MUL(y, sinv[3 + d])), MUL(z, sinv[6 + d]));
        for (int d = 0; d < 3; d++)
            f[d] = SUB(f[d], rintf(SUB(f[d], sfrac0[d])));
        s_wx[i] = ADD(ADD(MUL(f[0], cell[0]), MUL(f[1], cell[3])), MUL(f[2], cell[6]));
        s_wy[i] = ADD(ADD(MUL(f[0], cell[1]), MUL(f[1], cell[4])), MUL(f[2], cell[7]));
        s_wz[i] = ADD(ADD(MUL(f[0], cell[2]), MUL(f[1], cell[5])), MUL(f[2], cell[8]));
    }
    __syncthreads();

    // COM: shared tree levels 512..32 + shfl last 5; pairing preserved -> bit-identical
    {
        double s0 = 0.0, s1 = 0.0, s2 = 0.0, s3 = 0.0;
        for (int i = t; i < N; i += NTHR) {
            double m = (double)mass[i];
            s0 += m * (double)s_wx[i];
            s1 += m * (double)s_wy[i];
            s2 += m * (double)s_wz[i];
            s3 += m;
        }
        sd[t] = s0; sd[1024 + t] = s1; sd[2048 + t] = s2; sd[3072 + t] = s3;
        __syncthreads();
#pragma unroll
        for (int off = 512; off >= 32; off >>= 1) {
            if (t < off) {
                sd[t] += sd[t + off];
                sd[1024 + t] += sd[1024 + t + off];
                sd[2048 + t] += sd[2048 + t + off];
                sd[3072 + t] += sd[3072 + t + off];
            }
            __syncthreads();
        }
        if (wid == 0) {
            double x0 = sd[lane], x1 = sd[1024 + lane], x2 = sd[2048 + lane], x3 = sd[3072 + lane];
#pragma unroll
            for (int off = 16; off >= 1; off >>= 1) {
                x0 += __shfl_down_sync(0xffffffffu, x0, off);
                x1 += __shfl_down_sync(0xffffffffu, x1, off);
                x2 += __shfl_down_sync(0xffffffffu, x2, off);
                x3 += __shfl_down_sync(0xffffffffu, x3, off);
            }
            if (lane == 0) {
                float sm = (float)x3;
                scom[0] = DIV((float)x0, sm);
                scom[1] = DIV((float)x1, sm);
                scom[2] = DIV((float)x2, sm);
            }
        }
        __syncthreads();
    }

    // min/max over centered coords (order-free key reductions)
    {
        unsigned kmn[3] = {~0u, ~0u, ~0u}, kmx[3] = {0u, 0u, 0u};
        for (int i = t; i < N; i += NTHR) {
            unsigned k0 = fkey(SUB(s_wx[i], scom[0]));
            unsigned k1 = fkey(SUB(s_wy[i], scom[1]));
            unsigned k2 = fkey(SUB(s_wz[i], scom[2]));
            kmn[0] = min(kmn[0], k0); kmx[0] = max(kmx[0], k0);
            kmn[1] = min(kmn[1], k1); kmx[1] = max(kmx[1], k1);
            kmn[2] = min(kmn[2], k2); kmx[2] = max(kmx[2], k2);
        }
#pragma unroll
        for (int o = 16; o; o >>= 1) {
#pragma unroll
            for (int d = 0; d < 3; d++) {
                kmn[d] = min(kmn[d], __shfl_xor_sync(0xffffffffu, kmn[d], o));
                kmx[d] = max(kmx[d], __shfl_xor_sync(0xffffffffu, kmx[d], o));
            }
        }
        if (lane == 0) {
#pragma unroll
            for (int d = 0; d < 3; d++) {
                skey6[wid][d] = kmn[d];
                skey6[wid][3 + d] = kmx[d];
            }
        }
        __syncthreads();
        if (wid == 0) {
            unsigned vn0 = skey6[lane][0], vn1 = skey6[lane][1], vn2 = skey6[lane][2];
            unsigned vx0 = skey6[lane][3], vx1 = skey6[lane][4], vx2 = skey6[lane][5];
#pragma unroll
            for (int o = 16; o; o >>= 1) {
                vn0 = min(vn0, __shfl_xor_sync(0xffffffffu, vn0, o));
                vn1 = min(vn1, __shfl_xor_sync(0xffffffffu, vn1, o));
                vn2 = min(vn2, __shfl_xor_sync(0xffffffffu, vn2, o));
                vx0 = max(vx0, __shfl_xor_sync(0xffffffffu, vx0, o));
                vx1 = max(vx1, __shfl_xor_sync(0xffffffffu, vx1, o));
                vx2 = max(vx2, __shfl_xor_sync(0xffffffffu, vx2, o));
            }
            if (lane == 0) {
                float mn0 = SUB(SUB(fdec(vn0), 5.0f), 1e-6f);
                float mn1 = SUB(SUB(fdec(vn1), 5.0f), 1e-6f);
                float mn2 = SUB(SUB(fdec(vn2), 5.0f), 1e-6f);
                sminc[0] = mn0; sminc[1] = mn1; sminc[2] = mn2;
                smaxc[0] = ADD(SUB(fdec(vx0), mn0), 5.0f);
                smaxc[1] = ADD(SUB(fdec(vx1), mn1), 5.0f);
                smaxc[2] = ADD(SUB(fdec(vx2), mn2), 5.0f);
            }
        }
        __syncthreads();
    }

    // transform in place: s_w* := c2
    for (int i = t; i < N; i += NTHR) {
        s_wx[i] = SUB(SUB(s_wx[i], scom[0]), sminc[0]);
        s_wy[i] = SUB(SUB(s_wy[i], scom[1]), sminc[1]);
        s_wz[i] = SUB(SUB(s_wz[i], scom[2]), sminc[2]);
    }

    // ===== image build, block-local in shared (redundant per block) =====
    // Diagonal-cell factorization: shift components per dim are exactly the
    // per-dim entries of sshifts (cross terms are exact +/-0 adds), so
    // ADD(c2, comp) is bitwise equal to the reference's v = c2 + shifts[s].
    const float maxc0 = smaxc[0], maxc1 = smaxc[1], maxc2 = smaxc[2];
    float shxv[3], shyv[3], shzv[3];
#pragma unroll
    for (int j = 0; j < 3; j++) {
        shxv[j] = sshifts[(j * 9 + 4) * 3 + 0];   // shift (j-1, 0, 0) . x
        shyv[j] = sshifts[(10 + j * 3) * 3 + 1];  // shift (0, j-1, 0) . y
        shzv[j] = sshifts[(12 + j) * 3 + 2];      // shift (0, 0, j-1) . z
    }
    // zero histogram + cursors
    if (t < NCELL) { s_hist[t] = 0; s_fill[t] = 0; }
    __syncthreads();

    // pass 1: histogram
    for (int a = t; a < N; a += NTHR) {
        float c2x = s_wx[a], c2y = s_wy[a], c2z = s_wz[a];
        float vx[3], vy[3], vz[3];
        bool okx[3], oky[3], okz[3];
        int cxx[3], cyy[3], czz[3];
#pragma unroll
        for (int j = 0; j < 3; j++) {
            vx[j] = ADD(c2x, shxv[j]);
            vy[j] = ADD(c2y, shyv[j]);
            vz[j] = ADD(c2z, shzv[j]);
            okx[j] = (vx[j] > 0.f) && (vx[j] < maxc0);
            oky[j] = (vy[j] > 0.f) && (vy[j] < maxc1);
            okz[j] = (vz[j] > 0.f) && (vz[j] < maxc2);
            cxx[j] = min(max((int)floorf(DIV(vx[j], 5.0f)), 0), NGRID - 1);
            cyy[j] = min(max((int)floorf(DIV(vy[j], 5.0f)), 0), NGRID - 1);
            czz[j] = min(max((int)floorf(DIV(vz[j], 5.0f)), 0), NGRID - 1);
        }
#pragma unroll
        for (int jx = 0; jx < 3; jx++) {
            if (!okx[jx]) continue;
#pragma unroll
            for (int jy = 0; jy < 3; jy++) {
                if (!oky[jy]) continue;
#pragma unroll
                for (int jz = 0; jz < 3; jz++) {
                    if (!okz[jz]) continue;
                    int c = cxx[jx] + NGRID * (cyy[jy] + NGRID * czz[jz]);
                    atomicAdd(&s_hist[c], 1);
                }
            }
        }
    }
    __syncthreads();   // histogram complete before read (R5 lesson)

    // block-local scan -> scoff
    {
        int cv = (t < NCELL) ? s_hist[t] : 0;
        int ce = scanExcl1024(cv, stmp, lane, wid);
        if (t <= NCELL + 7) scoff[t] = ce;
        __syncthreads();
    }

    // pass 2: scatter into shared buckets (recompute; order within cell arbitrary)
    for (int a = t; a < N; a += NTHR) {
        float c2x = s_wx[a], c2y = s_wy[a], c2z = s_wz[a];
        float vx[3], vy[3], vz[3];
        bool okx[3], oky[3], okz[3];
        int cxx[3], cyy[3], czz[3];
#pragma unroll
        for (int j = 0; j < 3; j++) {
            vx[j] = ADD(c2x, shxv[j]);
            vy[j] = ADD(c2y, shyv[j]);
            vz[j] = ADD(c2z, shzv[j]);
            okx[j] = (vx[j] > 0.f) && (vx[j] < maxc0);
            oky[j] = (vy[j] > 0.f) && (vy[j] < maxc1);
            okz[j] = (vz[j] > 0.f) && (vz[j] < maxc2);
            cxx[j] = min(max((int)floorf(DIV(vx[j], 5.0f)), 0), NGRID - 1);
            cyy[j] = min(max((int)floorf(DIV(vy[j], 5.0f)), 0), NGRID - 1);
            czz[j] = min(max((int)floorf(DIV(vz[j], 5.0f)), 0), NGRID - 1);
        }
#pragma unroll
        for (int jx = 0; jx < 3; jx++) {
            if (!okx[jx]) continue;
#pragma unroll
            for (int jy = 0; jy < 3; jy++) {
                if (!oky[jy]) continue;
#pragma unroll
                for (int jz = 0; jz < 3; jz++) {
                    if (!okz[jz]) continue;
                    int c = cxx[jx] + NGRID * (cyy[jy] + NGRID * czz[jz]);
                    int idx = (jx * 9 + jy * 3 + jz) * N + a;
                    int pos = scoff[c] + atomicAdd(&s_fill[c], 1);
                    if (pos < MAXM)
                        s_img4[pos] = make_float4(vx[jx], vy[jy], vz[jz], __int_as_float(idx));
                }
            }
        }
    }
    __syncthreads();

    // ================= search: per-atom, all from shared =================
    {
        int w = wid * NBLK + b;
        int* sjw = sj + wid * MAXPA;
        int cur = 0;
        if (w < N) {
            float cx = s_wx[w], cy = s_wy[w], cz = s_wz[w];
            int ax = (int)floorf(DIV(cx, 5.0f));
            int ay = (int)floorf(DIV(cy, 5.0f));
            int az = (int)floorf(DIV(cz, 5.0f));
            int rsv[9], rlv[9];
#pragma unroll
            for (int q = 0; q < 9; q++) {
                int dz = q / 3 - 1, dy = q % 3 - 1;
                int row = (ax - 1) + NGRID * ((ay + dy) + NGRID * (az + dz));
                int sq = scoff[row];
                rsv[q] = sq;
                rlv[q] = scoff[row + 3] - sq;
            }
            int p1 = rlv[0];
            int p2 = p1 + rlv[1];
            int p3 = p2 + rlv[2];
            int p4 = p3 + rlv[3];
            int p5 = p4 + rlv[4];
            int p6 = p5 + rlv[5];
            int p7 = p6 + rlv[6];
            int p8 = p7 + rlv[7];
            int p9 = p8 + rlv[8];
            int b0 = rsv[0];
            int b1 = rsv[1] - p1;
            int b2 = rsv[2] - p2;
            int b3 = rsv[3] - p3;
            int b4 = rsv[4] - p4;
            int b5 = rsv[5] - p5;
            int b6 = rsv[6] - p6;
            int b7 = rsv[7] - p7;
            int b8 = rsv[8] - p8;
            for (int f0 = 0; f0 < p9; f0 += 32) {
                int f = f0 + lane;
                bool act = (f < p9);
                int base = (f < p1) ? b0
                         : (f < p2) ? b1
                         : (f < p3) ? b2
                         : (f < p4) ? b3
                         : (f < p5) ? b4
                         : (f < p6) ? b5
                         : (f < p7) ? b6
                         : (f < p8) ? b7
                         : b8;
                bool hit = false;
                int jidx = 0;
                if (act) {
                    float4 p = s_img4[f + base];
                    float ddx = SUB(cx, p.x);
                    float ddy = SUB(cy, p.y);
                    float ddz = SUB(cz, p.z);
                    float r2 = ADD(ADD(MUL(ddx, ddx), MUL(ddy, ddy)), MUL(ddz, ddz));
                    float dd = __fsqrt_rn(r2);
                    hit = (dd < 5.0f) && (dd > 0.001f);
                    jidx = __float_as_int(p.w);
                }
                unsigned bal = __ballot_sync(0xffffffffu, hit);
                if (hit) {
                    int slot = cur + __popc(bal & ((1u << lane) - 1u));
                    if (slot < MAXPA) sjw[slot] = jidx;
                }
                cur += __popc(bal);
            }
        }
        __syncwarp();
        int k = min(cur, MAXPA);
        // rank sort by image idx (unique) -> exact reference order
        int vals[6], rnks[6];
        int nn = 0;
        for (int i2 = lane; i2 < k; i2 += 32) {
            int v = sjw[i2];
            int r = 0;
            for (int q = 0; q < k; q++) r += (sjw[q] < v);
            vals[nn] = v;
            rnks[nn] = r;
            nn++;
        }
        __syncwarp();
        for (int q = 0; q < nn; q++) sjw[rnks[q]] = vals[q];
        if (w < N && lane == 0) g_cnt[w] = k;
    }
    gbar(++gen);  // the ONLY grid barrier: all counts visible

    // ================= offsets (redundant scan) + write =================
    {
        int cA[4];
        int myv = 0;
        int a0 = t * 4;
#pragma unroll
        for (int q = 0; q < 4; q++) {
            int a = a0 + q;
            cA[q] = (a < N) ? g_cnt[a] : 0;
            myv += cA[q];
        }
        int run = scanExcl1024(myv, stmp, lane, wid);
#pragma unroll
        for (int q = 0; q < 4; q++) {
            int a = a0 + q;
            if (a < N && (a & (NBLK - 1)) == b) sWoff[a >> 7] = run;
            run += cA[q];
        }
        __syncthreads();

        int w = wid * NBLK + b;
        if (w < N) {
            int off = sWoff[wid];
            int k = min(g_cnt[w], MAXPA);
            int* sjw = sj + wid * MAXPA;
            float fi = (float)w;
            for (int r = lane; r < k; r += 32) {
                int idx = sjw[r];
                int s = idx / N;
                int a = idx - s * N;
                int pos = off + r;
                out[pos] = fi;
                out[P + pos] = (float)a;
                out[2 * P + 3 * pos + 0] = sshifts[s * 3 + 0];
                out[2 * P + 3 * pos + 1] = sshifts[s * 3 + 1];
                out[2 * P + 3 * pos + 2] = sshifts[s * 3 + 2];
            }
        }
    }
}

// ---------------- launch ----------------
extern "C" void kernel_launch(void* const* d_in, const int* in_sizes, int n_in,
                              void* d_out, int out_size) {
    const int* period = (const int*)d_in[0];
    const float* coords = (const float*)d_in[1];
    const float* cell = (const float*)d_in[2];
    const float* mass = (const float*)d_in[3];
    float* out = (float*)d_out;

    int N = in_sizes[1] / 3;
    int P = out_size / 5;

    int smem = MAXM * 16 + 3 * 4 * N + 24576 + (NCELL + 8) * 4 + 64;
    cudaFuncSetAttribute(k_all, cudaFuncAttributeMaxDynamicSharedMemorySize, smem);
    k_all<<<NBLK, NTHR, smem>>>(cell, period, coords, mass, N, P, out);
}

// round 10
// speedup vs baseline: 1.3184x; 1.3184x over previous
#include <cuda_runtime.h>
#include <math.h>

#define MAXN 4096
#define MAXS 27
#define NGRID 10
#define NCELL (NGRID * NGRID * NGRID)
#define MAXPA 192
#define CAP 64

__device__ float  g_w[MAXN * 3];
__device__ float  g_shifts2[MAXS * 3];
__device__ int    g_S;
__device__ float  g_com2[3], g_minc2[3], g_maxc2[3];
__device__ int    g_fill[NCELL];          // zero at load; re-zeroed by k_write every run
__device__ float4 g_buck[NCELL * CAP];    // 1 MB fixed-capacity buckets
__device__ int    g_slab[MAXN * MAXPA];
__device__ int    g_cnt[MAXN];

#define MUL(a, b) __fmul_rn((a), (b))
#define ADD(a, b) __fadd_rn((a), (b))
#define SUB(a, b) __fsub_rn((a), (b))
#define DIV(a, b) __fdiv_rn((a), (b))

__device__ __forceinline__ unsigned fkey(float f) {
    unsigned u = __float_as_uint(f);
    return (u & 0x80000000u) ? ~u : (u | 0x80000000u);
}
__device__ __forceinline__ float fdec(unsigned k) {
    unsigned u = (k & 0x80000000u) ? (k & 0x7fffffffu) : ~k;
    return __uint_as_float(u);
}

// ---------------- kernel 1: setup (redundant per block) + partitioned wrap ----------------
__global__ void k_wrap(const float* __restrict__ cell, const int* __restrict__ period,
                       const float* __restrict__ coords, int N) {
    __shared__ float sinv[9], sfrac0[3];
    int t = threadIdx.x, b = blockIdx.x;
    if (t == 0) {
        float m00 = cell[0], m01 = cell[1], m02 = cell[2];
        float m10 = cell[3], m11 = cell[4], m12 = cell[5];
        float m20 = cell[6], m21 = cell[7], m22 = cell[8];
        float c00 = SUB(MUL(m11, m22), MUL(m12, m21));
        float c10 = SUB(MUL(m12, m20), MUL(m10, m22));
        float c20 = SUB(MUL(m10, m21), MUL(m11, m20));
        float det = ADD(ADD(MUL(m00, c00), MUL(m01, c10)), MUL(m02, c20));
        sinv[0] = DIV(c00, det);
        sinv[1] = DIV(SUB(MUL(m02, m21), MUL(m01, m22)), det);
        sinv[2] = DIV(SUB(MUL(m01, m12), MUL(m02, m11)), det);
        sinv[3] = DIV(c10, det);
        sinv[4] = DIV(SUB(MUL(m00, m22), MUL(m02, m20)), det);
        sinv[5] = DIV(SUB(MUL(m02, m10), MUL(m00, m12)), det);
        sinv[6] = DIV(c20, det);
        sinv[7] = DIV(SUB(MUL(m01, m20), MUL(m00, m21)), det);
        sinv[8] = DIV(SUB(MUL(m00, m11), MUL(m01, m10)), det);
        float x0 = coords[0], y0 = coords[1], z0 = coords[2];
        for (int d = 0; d < 3; d++)
            sfrac0[d] = ADD(ADD(MUL(x0, sinv[0 + d]), MUL(y0, sinv[3 + d])), MUL(z0, sinv[6 + d]));
        if (b == 0) {
            int nrep[3];
            for (int i = 0; i < 3; i++) {
                float r = DIV(5.0f, fabsf(cell[0 + i]));
                float r1 = DIV(5.0f, fabsf(cell[3 + i]));
                float r2 = DIV(5.0f, fabsf(cell[6 + i]));
                if (r1 < r) r = r1;
                if (r2 < r) r = r2;
                nrep[i] = (int)ceilf(r) * period[i];
            }
            int idx = 0;
            for (int a = -nrep[0]; a <= nrep[0]; a++)
                for (int bb = -nrep[1]; bb <= nrep[1]; bb++)
                    for (int c = -nrep[2]; c <= nrep[2]; c++) {
                        if (idx < MAXS) {
                            float fa = (float)a, fb = (float)bb, fc = (float)c;
                            for (int d = 0; d < 3; d++)
                                g_shifts2[idx * 3 + d] =
                                    ADD(ADD(MUL(fa, cell[0 + d]), MUL(fb, cell[3 + d])), MUL(fc, cell[6 + d]));
                        }
                        idx++;
                    }
            g_S = (idx > MAXS) ? MAXS : idx;
        }
    }
    __syncthreads();
    int i = b * 256 + t;
    if (i < N) {
        float x = coords[i * 3 + 0], y = coords[i * 3 + 1], z = coords[i * 3 + 2];
        float f[3];
        for (int d = 0; d < 3; d++)
            f[d] = ADD(ADD(MUL(x, sinv[0 + d]), MUL(y, sinv[3 + d])), MUL(z, sinv[6 + d]));
        for (int d = 0; d < 3; d++)
            f[d] = SUB(f[d], rintf(SUB(f[d], sfrac0[d])));
        g_w[i * 3 + 0] = ADD(ADD(MUL(f[0], cell[0]), MUL(f[1], cell[3])), MUL(f[2], cell[6]));
        g_w[i * 3 + 1] = ADD(ADD(MUL(f[0], cell[1]), MUL(f[1], cell[4])), MUL(f[2], cell[7]));
        g_w[i * 3 + 2] = ADD(ADD(MUL(f[0], cell[2]), MUL(f[1], cell[5])), MUL(f[2], cell[8]));
    }
}

// ---------------- kernel 2: COM + min/max (single block, bit-identical order) ----------------
__global__ __launch_bounds__(1024, 1)
void k_reduce(const float* __restrict__ mass, int N) {
    __shared__ double sd[4096];
    __shared__ unsigned skey6[32][6];
    __shared__ float scom[3];
    int t = threadIdx.x, lane = t & 31, wid = t >> 5;

    double s0 = 0.0, s1 = 0.0, s2 = 0.0, s3 = 0.0;
    for (int i = t; i < N; i += 1024) {
        double m = (double)mass[i];
        s0 += m * (double)g_w[i * 3 + 0];
        s1 += m * (double)g_w[i * 3 + 1];
        s2 += m * (double)g_w[i * 3 + 2];
        s3 += m;
    }
    sd[t] = s0; sd[1024 + t] = s1; sd[2048 + t] = s2; sd[3072 + t] = s3;
    __syncthreads();
#pragma unroll
    for (int off = 512; off >= 32; off >>= 1) {
        if (t < off) {
            sd[t] += sd[t + off];
            sd[1024 + t] += sd[1024 + t + off];
            sd[2048 + t] += sd[2048 + t + off];
            sd[3072 + t] += sd[3072 + t + off];
        }
        __syncthreads();
    }
    if (wid == 0) {
        double x0 = sd[lane], x1 = sd[1024 + lane], x2 = sd[2048 + lane], x3 = sd[3072 + lane];
#pragma unroll
        for (int off = 16; off >= 1; off >>= 1) {
            x0 += __shfl_down_sync(0xffffffffu, x0, off);
            x1 += __shfl_down_sync(0xffffffffu, x1, off);
            x2 += __shfl_down_sync(0xffffffffu, x2, off);
            x3 += __shfl_down_sync(0xffffffffu, x3, off);
        }
        if (lane == 0) {
            float sm = (float)x3;
            scom[0] = DIV((float)x0, sm);
            scom[1] = DIV((float)x1, sm);
            scom[2] = DIV((float)x2, sm);
            g_com2[0] = scom[0]; g_com2[1] = scom[1]; g_com2[2] = scom[2];
        }
    }
    __syncthreads();

    unsigned kmn[3] = {~0u, ~0u, ~0u}, kmx[3] = {0u, 0u, 0u};
    for (int i = t; i < N; i += 1024) {
        unsigned k0 = fkey(SUB(g_w[i * 3 + 0], scom[0]));
        unsigned k1 = fkey(SUB(g_w[i * 3 + 1], scom[1]));
        unsigned k2 = fkey(SUB(g_w[i * 3 + 2], scom[2]));
        kmn[0] = min(kmn[0], k0); kmx[0] = max(kmx[0], k0);
        kmn[1] = min(kmn[1], k1); kmx[1] = max(kmx[1], k1);
        kmn[2] = min(kmn[2], k2); kmx[2] = max(kmx[2], k2);
    }
#pragma unroll
    for (int o = 16; o; o >>= 1) {
#pragma unroll
        for (int d = 0; d < 3; d++) {
            kmn[d] = min(kmn[d], __shfl_xor_sync(0xffffffffu, kmn[d], o));
            kmx[d] = max(kmx[d], __shfl_xor_sync(0xffffffffu, kmx[d], o));
        }
    }
    if (lane == 0) {
#pragma unroll
        for (int d = 0; d < 3; d++) {
            skey6[wid][d] = kmn[d];
            skey6[wid][3 + d] = kmx[d];
        }
    }
    __syncthreads();
    if (wid == 0) {
        unsigned vn0 = skey6[lane][0], vn1 = skey6[lane][1], vn2 = skey6[lane][2];
        unsigned vx0 = skey6[lane][3], vx1 = skey6[lane][4], vx2 = skey6[lane][5];
#pragma unroll
        for (int o = 16; o; o >>= 1) {
            vn0 = min(vn0, __shfl_xor_sync(0xffffffffu, vn0, o));
            vn1 = min(vn1, __shfl_xor_sync(0xffffffffu, vn1, o));
            vn2 = min(vn2, __shfl_xor_sync(0xffffffffu, vn2, o));
            vx0 = max(vx0, __shfl_xor_sync(0xffffffffu, vx0, o));
            vx1 = max(vx1, __shfl_xor_sync(0xffffffffu, vx1, o));
            vx2 = max(vx2, __shfl_xor_sync(0xffffffffu, vx2, o));
        }
        if (lane == 0) {
            float mn0 = SUB(SUB(fdec(vn0), 5.0f), 1e-6f);
            float mn1 = SUB(SUB(fdec(vn1), 5.0f), 1e-6f);
            float mn2 = SUB(SUB(fdec(vn2), 5.0f), 1e-6f);
            g_minc2[0] = mn0; g_minc2[1] = mn1; g_minc2[2] = mn2;
            g_maxc2[0] = ADD(SUB(fdec(vx0), mn0), 5.0f);
            g_maxc2[1] = ADD(SUB(fdec(vx1), mn1), 5.0f);
            g_maxc2[2] = ADD(SUB(fdec(vx2), mn2), 5.0f);
        }
    }
}

// ---------------- kernel 3: images -> fixed-capacity buckets (one thread per image) --------
__global__ void k_image(int N) {
    int gt = blockIdx.x * 256 + threadIdx.x;
    int NS = g_S * N;
    if (gt >= NS) return;
    int s = gt / N;
    int a = gt - s * N;
    float c2x = SUB(SUB(g_w[a * 3 + 0], g_com2[0]), g_minc2[0]);
    float c2y = SUB(SUB(g_w[a * 3 + 1], g_com2[1]), g_minc2[1]);
    float c2z = SUB(SUB(g_w[a * 3 + 2], g_com2[2]), g_minc2[2]);
    float v0 = ADD(c2x, g_shifts2[s * 3 + 0]);
    float v1 = ADD(c2y, g_shifts2[s * 3 + 1]);
    float v2 = ADD(c2z, g_shifts2[s * 3 + 2]);
    if ((v0 > 0.f) && (v0 < g_maxc2[0]) && (v1 > 0.f) && (v1 < g_maxc2[1]) &&
        (v2 > 0.f) && (v2 < g_maxc2[2])) {
        int cx = min(max((int)floorf(DIV(v0, 5.0f)), 0), NGRID - 1);
        int cy = min(max((int)floorf(DIV(v1, 5.0f)), 0), NGRID - 1);
        int cz = min(max((int)floorf(DIV(v2, 5.0f)), 0), NGRID - 1);
        int c = cx + NGRID * (cy + NGRID * cz);
        int pos = atomicAdd(&g_fill[c], 1);
        if (pos < CAP)
            g_buck[c * CAP + pos] = make_float4(v0, v1, v2, __int_as_float(gt));
    }
}

// ---------------- kernel 4: per-atom search (flattened 27-bucket stream) + rank sort -------
__global__ void k_search(int N) {
    __shared__ int sj[8][MAXPA];
    __shared__ int spre[8][32];
    __shared__ int sadj[8][32];
    int t = threadIdx.x, lane = t & 31, wid = t >> 5;
    int w = blockIdx.x * 8 + wid;
    if (w >= N) return;

    float cx = SUB(SUB(g_w[w * 3 + 0], g_com2[0]), g_minc2[0]);
    float cy = SUB(SUB(g_w[w * 3 + 1], g_com2[1]), g_minc2[1]);
    float cz = SUB(SUB(g_w[w * 3 + 2], g_com2[2]), g_minc2[2]);
    int ax = (int)floorf(DIV(cx, 5.0f));
    int ay = (int)floorf(DIV(cy, 5.0f));
    int az = (int)floorf(DIV(cz, 5.0f));

    // lane q < 27: stencil cell counts + bases
    int cnt = 0, base = 0;
    if (lane < 27) {
        int qx = lane % 3, qr = lane / 3;
        int qy = qr % 3, qz = qr / 3;
        int c = (ax + qx - 1) + NGRID * ((ay + qy - 1) + NGRID * (az + qz - 1));
        cnt = min(g_fill[c], CAP);
        base = c * CAP;
    }
    int incl = cnt;
#pragma unroll
    for (int o = 1; o < 32; o <<= 1) {
        int y = __shfl_up_sync(0xffffffffu, incl, o);
        if (lane >= o) incl += y;
    }
    int excl = incl - cnt;
    int T = __shfl_sync(0xffffffffu, incl, 31);
    spre[wid][lane] = excl;           // lanes >= 27 hold T (empty tail segments)
    sadj[wid][lane] = base - excl;
    __syncwarp();

    int* sjw = sj[wid];
    int cur = 0;
    for (int f0 = 0; f0 < T; f0 += 32) {
        int f = f0 + lane;
        bool hit = false;
        int jidx = 0;
        if (f < T) {
            // binary search: largest q with spre[q] <= f
            int lo = 0;
#pragma unroll
            for (int step = 16; step; step >>= 1) {
                int nq = lo + step;
                if (nq < 32 && spre[wid][nq] <= f) lo = nq;
            }
            float4 p = g_buck[sadj[wid][lo] + f];
            float ddx = SUB(cx, p.x);
            float ddy = SUB(cy, p.y);
            float ddz = SUB(cz, p.z);
            float r2 = ADD(ADD(MUL(ddx, ddx), MUL(ddy, ddy)), MUL(ddz, ddz));
            float dd = __fsqrt_rn(r2);
            hit = (dd < 5.0f) && (dd > 0.001f);
            jidx = __float_as_int(p.w);
        }
        unsigned bal = __ballot_sync(0xffffffffu, hit);
        if (hit) {
            int slot = cur + __popc(bal & ((1u << lane) - 1u));
            if (slot < MAXPA) sjw[slot] = jidx;
        }
        cur += __popc(bal);
    }
    __syncwarp();
    int k = min(cur, MAXPA);
    // rank sort by image idx (unique) -> exact reference order
    int vals[6], rnks[6];
    int nn = 0;
    for (int i2 = lane; i2 < k; i2 += 32) {
        int v = sjw[i2];
        int r = 0;
        for (int q = 0; q < k; q++) r += (sjw[q] < v);
        vals[nn] = v;
        rnks[nn] = r;
        nn++;
    }
    __syncwarp();
    for (int q = 0; q < nn; q++) sjw[rnks[q]] = vals[q];
    __syncwarp();
    for (int r = lane; r < k; r += 32) g_slab[w * MAXPA + r] = sjw[r];
    if (lane == 0) g_cnt[w] = k;
}

// ---------------- kernel 5: redundant offset scan + ordered write + cleanup ----------------
__global__ void k_write(int N, int P, float* __restrict__ out) {
    __shared__ int soff[MAXN];
    __shared__ int stmp[8];
    int t = threadIdx.x, lane = t & 31, wid = t >> 5;

    // re-zero g_fill for next run (previous kernels done; none here reads it)
    for (int i = blockIdx.x * 256 + t; i < NCELL; i += gridDim.x * 256) g_fill[i] = 0;

    // redundant block-local scan of g_cnt -> soff
    const int E = (MAXN + 255) / 256;  // 16
    int lc[E];
    int b0 = t * ((N + 255) / 256);
    int e0 = min(b0 + (N + 255) / 256, N);
    int ls = 0;
    for (int i = b0; i < e0; i++) {
        int v = g_cnt[i];
        lc[i - b0] = v;
        ls += v;
    }
    int x = ls;
#pragma unroll
    for (int o = 1; o < 32; o <<= 1) {
        int y = __shfl_up_sync(0xffffffffu, x, o);
        if (lane >= o) x += y;
    }
    if (lane == 31) stmp[wid] = x;
    __syncthreads();
    if (wid == 0 && lane < 8) {
        int s = stmp[lane];
#pragma unroll
        for (int o = 1; o < 8; o <<= 1) {
            int y = __shfl_up_sync(0xffu, s, o);
            if (lane >= o) s += y;
        }
        stmp[lane] = s;
    }
    __syncthreads();
    int run = (wid ? stmp[wid - 1] : 0) + x - ls;
    for (int i = b0; i < e0; i++) {
        soff[i] = run;
        run += lc[i - b0];
    }
    __syncthreads();

    int w = blockIdx.x * 8 + wid;
    if (w >= N) return;
    int off = soff[w];
    int k = min(g_cnt[w], MAXPA);
    float fi = (float)w;
    for (int r = lane; r < k; r += 32) {
        int idx = g_slab[w * MAXPA + r];
        int s = idx / N;
        int a = idx - s * N;
        int pos = off + r;
        out[pos] = fi;
        out[P + pos] = (float)a;
        out[2 * P + 3 * pos + 0] = g_shifts2[s * 3 + 0];
        out[2 * P + 3 * pos + 1] = g_shifts2[s * 3 + 1];
        out[2 * P + 3 * pos + 2] = g_shifts2[s * 3 + 2];
    }
}

// ---------------- launch ----------------
extern "C" void kernel_launch(void* const* d_in, const int* in_sizes, int n_in,
                              void* d_out, int out_size) {
    const int* period = (const int*)d_in[0];
    const float* coords = (const float*)d_in[1];
    const float* cell = (const float*)d_in[2];
    const float* mass = (const float*)d_in[3];
    float* out = (float*)d_out;

    int N = in_sizes[1] / 3;
    int P = out_size / 5;
    int WB = (N + 255) / 256;
    int IB = (27 * N + 255) / 256;
    int SB = (N + 7) / 8;

    k_wrap<<<WB, 256>>>(cell, period, coords, N);
    k_reduce<<<1, 1024>>>(mass, N);
    k_image<<<IB, 256>>>(N);
    k_search<<<SB, 256>>>(N);
    k_write<<<SB, 256>>>(N, P, out);
}